// round 8
// baseline (speedup 1.0000x reference)
#include <cuda_runtime.h>
#include <cstdint>

// Problem constants (fixed by the dataset)
#define NN      12288
#define IND     16
#define HID     256
#define NC      16
#define STRIDE  192     // per-column capacity; deg ~ Binom(N, 64/N) -> >15 sigma
#define BNH     16      // nodes per block in fused h1y2
#define NPBA    16      // nodes per block in aggregation kernels (16 threads/node)

// extract pipeline geometry
#define XGRID   296     // 2 persistent blocks per SM (148 SMs)
#define XSTG    5       // pipeline stages
#define XCB     8192    // bytes per stage chunk (8 KB)
#define XCW     512     // uint4 words per chunk
#define XCPR    6       // chunks per row (49152 / 8192)

// ---- scratch (static device arrays; no cudaMalloc allowed) ----
__device__ int   g_cnt[NN];               // zero-initialized at load; re-zeroed by k_softmax
__device__ int   g_rows[NN * STRIDE];
__device__ float g_dis[NN];
__device__ float g_dx[NN * IND];          // dis[i] * x[i]
__device__ float g_s[NN * IND];           // aggregated pre-transform features
__device__ float g_y2[NN * NC];
__device__ float g_cmax[NC];
__device__ float g_csum[NC];

__device__ __forceinline__ unsigned int smem_u32(const void* p) {
    unsigned int a;
    asm("{ .reg .u64 t; cvta.to.shared.u64 t, %1; cvt.u32.u64 %0, t; }" : "=r"(a) : "l"(p));
    return a;
}

__device__ __forceinline__ void mbar_wait(unsigned int mb, unsigned int ph) {
    asm volatile(
        "{\n\t"
        ".reg .pred P;\n\t"
        "LW_%=:\n\t"
        "mbarrier.try_wait.parity.acquire.cta.shared::cta.b64 P, [%0], %1, 0x989680;\n\t"
        "@P bra.uni LD_%=;\n\t"
        "bra.uni LW_%=;\n\t"
        "LD_%=:\n\t"
        "}"
        :: "r"(mb), "r"(ph) : "memory");
}

__device__ __forceinline__ void bulk_issue(unsigned int mb, unsigned int dst, const float* src) {
    asm volatile(
        "mbarrier.arrive.expect_tx.shared.b64 _, [%0], %3;\n\t"
        "cp.async.bulk.shared::cta.global.mbarrier::complete_tx::bytes [%1], [%2], %3, [%0];"
        :: "r"(mb), "r"(dst), "l"(src), "r"((unsigned int)XCB) : "memory");
}

__device__ __forceinline__ void emit4(const uint4& v, int j, int i) {
    if (v.x) { int p = atomicAdd(&g_cnt[j + 0], 1); if (p < STRIDE) g_rows[(j + 0) * STRIDE + p] = i; }
    if (v.y) { int p = atomicAdd(&g_cnt[j + 1], 1); if (p < STRIDE) g_rows[(j + 1) * STRIDE + p] = i; }
    if (v.z) { int p = atomicAdd(&g_cnt[j + 2], 1); if (p < STRIDE) g_rows[(j + 2) * STRIDE + p] = i; }
    if (v.w) { int p = atomicAdd(&g_cnt[j + 3], 1); if (p < STRIDE) g_rows[(j + 3) * STRIDE + p] = i; }
}

// ---- 1: persistent bulk-async streaming pass over A ----
// cp.async.bulk keeps 40KB/block (80KB/SM) in flight via mbarrier tx tracking,
// bypassing the ~64-entry per-SM LDG queue that capped the LDG path at ~4.5 TB/s.
__global__ void __launch_bounds__(256) k_extract(const float* __restrict__ A) {
    __shared__ __align__(16) uint4 buf[XSTG][XCW];       // 40 KB
    __shared__ unsigned long long mbar[XSTG];
    int tid = threadIdx.x;
    unsigned int mb0 = smem_u32(mbar);
    if (tid == 0) {
        #pragma unroll
        for (int s2 = 0; s2 < XSTG; s2++)
            asm volatile("mbarrier.init.shared.b64 [%0], 1;" :: "r"(mb0 + s2 * 8) : "memory");
        asm volatile("fence.proxy.async.shared::cta;" ::: "memory");
    }
    __syncthreads();

    int n_rows = (NN - (int)blockIdx.x + XGRID - 1) / XGRID;
    int n_chunks = n_rows * XCPR;

    int issue_i = blockIdx.x, issue_p = 0;
    int pro = n_chunks < XSTG ? n_chunks : XSTG;
    if (tid == 0) {
        for (int m = 0; m < pro; m++) {
            bulk_issue(mb0 + m * 8, smem_u32(&buf[m][0]),
                       A + (size_t)issue_i * NN + issue_p * (XCB / 4));
            if (++issue_p == XCPR) { issue_p = 0; issue_i += XGRID; }
        }
    }

    int cons_i = blockIdx.x, cons_p = 0;
    int s = 0, ph = 0;
    for (int k = 0; k < n_chunks; k++) {
        mbar_wait(mb0 + s * 8, ph);
        int base = cons_p * (XCB / 4) + tid * 4;
        uint4 v0 = buf[s][tid];
        uint4 v1 = buf[s][tid + 256];
        if (v0.x | v0.y | v0.z | v0.w) emit4(v0, base, cons_i);
        if (v1.x | v1.y | v1.z | v1.w) emit4(v1, base + 1024, cons_i);
        __syncthreads();          // stage fully consumed before refill
        if (tid == 0 && k + XSTG < n_chunks) {
            bulk_issue(mb0 + s * 8, smem_u32(&buf[s][0]),
                       A + (size_t)issue_i * NN + issue_p * (XCB / 4));
            if (++issue_p == XCPR) { issue_p = 0; issue_i += XGRID; }
        }
        if (++cons_p == XCPR) { cons_p = 0; cons_i += XGRID; }
        if (++s == XSTG) { s = 0; ph ^= 1; }
    }
}

// ---- 2: dis = rsqrt(cnt+1); dx = dis * x ----
__global__ void k_prep(const float* __restrict__ x) {
    int t = blockIdx.x * blockDim.x + threadIdx.x;
    if (t >= NN) return;
    float dis = rsqrtf((float)(g_cnt[t] + 1));
    g_dis[t] = dis;
    const float4* xr = (const float4*)(x + t * IND);
    float4* dr = (float4*)(g_dx + t * IND);
    #pragma unroll
    for (int q = 0; q < 4; q++) {
        float4 v = xr[q];
        v.x *= dis; v.y *= dis; v.z *= dis; v.w *= dis;
        dr[q] = v;
    }
}

// ---- helpers for the split-edge gather ----
__device__ __forceinline__ void f4add(float4& a, const float4& v) {
    a.x += v.x; a.y += v.y; a.z += v.z; a.w += v.w;
}
__device__ __forceinline__ float4 f4red4(float4 a0, const float4& a1) {
    f4add(a0, a1);
    #pragma unroll
    for (int off = 4; off <= 8; off <<= 1) {
        a0.x += __shfl_xor_sync(0xffffffffu, a0.x, off);
        a0.y += __shfl_xor_sync(0xffffffffu, a0.y, off);
        a0.z += __shfl_xor_sync(0xffffffffu, a0.z, off);
        a0.w += __shfl_xor_sync(0xffffffffu, a0.w, off);
    }
    return a0;
}

// ---- 3: input-space aggregation: s[j] = dis_j * (dx[j] + sum_{i in col j} dx[i]) ----
// 16 threads/node: 4 float4 lanes x 4 edge-splits, 2 accumulators each (measured best).
__global__ void k_xagg() {
    __shared__ int sl[NPBA][STRIDE];   // 12 KB
    __shared__ int sdd[NPBA];
    int jb = blockIdx.x * NPBA;
    for (int t = threadIdx.x; t < NPBA * STRIDE; t += blockDim.x)
        ((int*)sl)[t] = g_rows[jb * STRIDE + t];
    if (threadIdx.x < NPBA) sdd[threadIdx.x] = min(g_cnt[jb + threadIdx.x], STRIDE);
    __syncthreads();
    int n = threadIdx.x >> 4;
    int r = (threadIdx.x >> 2) & 3;
    int q = threadIdx.x & 3;
    int j = jb + n;
    int d = sdd[n];
    float4 a0 = make_float4(0.f, 0.f, 0.f, 0.f), a1 = a0;
    if (r == 0) a0 = *(const float4*)(g_dx + j * IND + q * 4);   // self loop (+I)
    int e = r;
    for (; e + 4 < d; e += 8) {
        const float4 v0 = *(const float4*)(g_dx + sl[n][e]     * IND + q * 4);
        const float4 v1 = *(const float4*)(g_dx + sl[n][e + 4] * IND + q * 4);
        f4add(a0, v0); f4add(a1, v1);
    }
    if (e < d) f4add(a0, *(const float4*)(g_dx + sl[n][e] * IND + q * 4));
    float4 s = f4red4(a0, a1);
    if (r == 0) {
        float dj = g_dis[j];
        s.x *= dj; s.y *= dj; s.z *= dj; s.w *= dj;
        *(float4*)(g_s + j * IND + q * 4) = s;
    }
}

// ---- 4: fused per-node MLP: y2 = dis .* (relu(s@W1 + b1) @ W2) ----
__global__ void k_h1y2(const float* __restrict__ W1, const float* __restrict__ b1,
                       const float* __restrict__ W2) {
    __shared__ float ss[BNH][IND];
    __shared__ float sh[BNH][HID + 1];
    int jb = blockIdx.x * BNH;
    if (threadIdx.x < BNH * IND) ((float*)ss)[threadIdx.x] = g_s[jb * IND + threadIdx.x];
    __syncthreads();
    int c = threadIdx.x;
    float w[IND];
    #pragma unroll
    for (int k = 0; k < IND; k++) w[k] = __ldg(&W1[k * HID + c]);
    float bb = __ldg(&b1[c]);
    #pragma unroll
    for (int n = 0; n < BNH; n++) {
        float acc = bb;
        #pragma unroll
        for (int k = 0; k < IND; k++) acc += ss[n][k] * w[k];
        sh[n][c] = fmaxf(acc, 0.0f);
    }
    __syncthreads();
    int n = threadIdx.x / NC, cc = threadIdx.x % NC;
    float acc = 0.0f;
    #pragma unroll 8
    for (int k = 0; k < HID; k++) acc += sh[n][k] * __ldg(&W2[k * NC + cc]);
    int j = jb + n;
    g_y2[j * NC + cc] = g_dis[j] * acc;
}

// ---- 5: layer-2 aggregation + bias + skip(x) -> logits in d_out ----
__global__ void k_agg2(const float* __restrict__ x, const float* __restrict__ b2,
                       float* __restrict__ out) {
    __shared__ int sl[NPBA][STRIDE];
    __shared__ int sdd[NPBA];
    int jb = blockIdx.x * NPBA;
    for (int t = threadIdx.x; t < NPBA * STRIDE; t += blockDim.x)
        ((int*)sl)[t] = g_rows[jb * STRIDE + t];
    if (threadIdx.x < NPBA) sdd[threadIdx.x] = min(g_cnt[jb + threadIdx.x], STRIDE);
    __syncthreads();
    int n = threadIdx.x >> 4;
    int r = (threadIdx.x >> 2) & 3;
    int q = threadIdx.x & 3;
    int j = jb + n;
    int d = sdd[n];
    float4 a0 = make_float4(0.f, 0.f, 0.f, 0.f), a1 = a0;
    if (r == 0) a0 = *(const float4*)(g_y2 + j * NC + q * 4);    // self loop
    int e = r;
    for (; e + 4 < d; e += 8) {
        const float4 v0 = *(const float4*)(g_y2 + sl[n][e]     * NC + q * 4);
        const float4 v1 = *(const float4*)(g_y2 + sl[n][e + 4] * NC + q * 4);
        f4add(a0, v0); f4add(a1, v1);
    }
    if (e < d) f4add(a0, *(const float4*)(g_y2 + sl[n][e] * NC + q * 4));
    float4 s = f4red4(a0, a1);
    if (r == 0) {
        float dj = g_dis[j];
        const float4 xb = *(const float4*)(x + j * IND + q * 4);
        const float4 bb = *(const float4*)(b2 + q * 4);
        float4 rr;
        rr.x = dj * s.x + bb.x + xb.x;
        rr.y = dj * s.y + bb.y + xb.y;
        rr.z = dj * s.z + bb.z + xb.z;
        rr.w = dj * s.w + bb.w + xb.w;
        *(float4*)(out + j * NC + q * 4) = rr;
    }
}

// ---- 6: per-class (axis=0) max and sum(exp) ----
__global__ void k_colreduce(const float* __restrict__ out) {
    int c = blockIdx.x;
    __shared__ float red[256];
    float m = -1e30f;
    for (int j = threadIdx.x; j < NN; j += 256) m = fmaxf(m, out[j * NC + c]);
    red[threadIdx.x] = m; __syncthreads();
    for (int s = 128; s > 0; s >>= 1) {
        if (threadIdx.x < s) red[threadIdx.x] = fmaxf(red[threadIdx.x], red[threadIdx.x + s]);
        __syncthreads();
    }
    m = red[0]; __syncthreads();
    float s = 0.0f;
    for (int j = threadIdx.x; j < NN; j += 256) s += expf(out[j * NC + c] - m);
    red[threadIdx.x] = s; __syncthreads();
    for (int st = 128; st > 0; st >>= 1) {
        if (threadIdx.x < st) red[threadIdx.x] += red[threadIdx.x + st];
        __syncthreads();
    }
    if (threadIdx.x == 0) { g_cmax[c] = m; g_csum[c] = red[0]; }
}

// ---- 7: normalize in place + re-zero counters for the next graph replay ----
__global__ void k_softmax(float* __restrict__ out) {
    int t = blockIdx.x * blockDim.x + threadIdx.x;
    if (t < NN) g_cnt[t] = 0;          // statics start zeroed; every run ends zeroed
    if (t < NN * NC) {
        int c = t & (NC - 1);
        out[t] = expf(out[t] - g_cmax[c]) / g_csum[c];
    }
}

extern "C" void kernel_launch(void* const* d_in, const int* in_sizes, int n_in,
                              void* d_out, int out_size) {
    const float* A  = (const float*)d_in[0];
    const float* x  = (const float*)d_in[1];
    const float* W1 = (const float*)d_in[2];
    const float* b1 = (const float*)d_in[3];
    const float* W2 = (const float*)d_in[4];
    const float* b2 = (const float*)d_in[5];
    float* out = (float*)d_out;

    k_extract<<<XGRID, 256>>>(A);
    k_prep<<<(NN + 255) / 256, 256>>>(x);
    k_xagg<<<NN / NPBA, NPBA * 16>>>();
    k_h1y2<<<NN / BNH, HID>>>(W1, b1, W2);
    k_agg2<<<NN / NPBA, NPBA * 16>>>(x, b2, out);
    k_colreduce<<<NC, 256>>>(out);
    k_softmax<<<(NN * NC + 255) / 256, 256>>>(out);
}

// round 9
// speedup vs baseline: 2.1280x; 2.1280x over previous
#include <cuda_runtime.h>
#include <cstdint>

// Problem constants (fixed by the dataset)
#define NN      12288
#define IND     16
#define HID     256
#define NC      16
#define STRIDE  192     // per-column capacity; deg ~ Binom(N, 64/N) -> >15 sigma
#define BNH     16      // nodes per block in fused h1y2
#define NPBA    16      // nodes per block in aggregation kernels (16 threads/node)
#define HPAD    (HID + 4)   // padded smem row stride (260 floats)

// ---- scratch (static device arrays; no cudaMalloc allowed) ----
__device__ int   g_cnt[NN];               // zero at load; re-zeroed by k_softmax each run
__device__ int   g_rows[NN * STRIDE];
__device__ float g_dis[NN];
__device__ float g_dx[NN * IND];          // dis[i] * x[i]
__device__ float g_s[NN * IND];           // aggregated pre-transform features
__device__ float g_y2[NN * NC];
__device__ float g_cmax[NC];
__device__ float g_csum[NC];

// ---- 1: single streaming pass over A (R3 form: measured best at ~4.6 TB/s) ----
__global__ void k_extract(const float* __restrict__ A) {
    int i = blockIdx.x;
    const float4* row = (const float4*)(A + (size_t)i * NN);
    for (int t = threadIdx.x; t < NN / 4; t += blockDim.x) {
        float4 v = __ldcs(&row[t]);
        int j = t * 4;
        if (v.x != 0.0f) { int p = atomicAdd(&g_cnt[j + 0], 1); if (p < STRIDE) g_rows[(j + 0) * STRIDE + p] = i; }
        if (v.y != 0.0f) { int p = atomicAdd(&g_cnt[j + 1], 1); if (p < STRIDE) g_rows[(j + 1) * STRIDE + p] = i; }
        if (v.z != 0.0f) { int p = atomicAdd(&g_cnt[j + 2], 1); if (p < STRIDE) g_rows[(j + 2) * STRIDE + p] = i; }
        if (v.w != 0.0f) { int p = atomicAdd(&g_cnt[j + 3], 1); if (p < STRIDE) g_rows[(j + 3) * STRIDE + p] = i; }
    }
}

// ---- 2: dis = rsqrt(cnt+1); dx = dis * x ----
__global__ void k_prep(const float* __restrict__ x) {
    int t = blockIdx.x * blockDim.x + threadIdx.x;
    if (t >= NN) return;
    float dis = rsqrtf((float)(g_cnt[t] + 1));
    g_dis[t] = dis;
    const float4* xr = (const float4*)(x + t * IND);
    float4* dr = (float4*)(g_dx + t * IND);
    #pragma unroll
    for (int q = 0; q < 4; q++) {
        float4 v = xr[q];
        v.x *= dis; v.y *= dis; v.z *= dis; v.w *= dis;
        dr[q] = v;
    }
}

// ---- helpers for the split-edge gather ----
__device__ __forceinline__ void f4add(float4& a, const float4& v) {
    a.x += v.x; a.y += v.y; a.z += v.z; a.w += v.w;
}
__device__ __forceinline__ float4 f4red4(float4 a0, const float4& a1) {
    f4add(a0, a1);
    #pragma unroll
    for (int off = 4; off <= 8; off <<= 1) {
        a0.x += __shfl_xor_sync(0xffffffffu, a0.x, off);
        a0.y += __shfl_xor_sync(0xffffffffu, a0.y, off);
        a0.z += __shfl_xor_sync(0xffffffffu, a0.z, off);
        a0.w += __shfl_xor_sync(0xffffffffu, a0.w, off);
    }
    return a0;
}

// ---- 3: input-space aggregation (R3 geometry: measured best 11.1us) ----
__global__ void k_xagg() {
    __shared__ int sl[NPBA][STRIDE];   // 12 KB
    __shared__ int sdd[NPBA];
    int jb = blockIdx.x * NPBA;
    for (int t = threadIdx.x; t < NPBA * STRIDE; t += blockDim.x)
        ((int*)sl)[t] = g_rows[jb * STRIDE + t];
    if (threadIdx.x < NPBA) sdd[threadIdx.x] = min(g_cnt[jb + threadIdx.x], STRIDE);
    __syncthreads();
    int n = threadIdx.x >> 4;
    int r = (threadIdx.x >> 2) & 3;
    int q = threadIdx.x & 3;
    int j = jb + n;
    int d = sdd[n];
    float4 a0 = make_float4(0.f, 0.f, 0.f, 0.f), a1 = a0;
    if (r == 0) a0 = *(const float4*)(g_dx + j * IND + q * 4);   // self loop (+I)
    int e = r;
    for (; e + 4 < d; e += 8) {
        const float4 v0 = *(const float4*)(g_dx + sl[n][e]     * IND + q * 4);
        const float4 v1 = *(const float4*)(g_dx + sl[n][e + 4] * IND + q * 4);
        f4add(a0, v0); f4add(a1, v1);
    }
    if (e < d) f4add(a0, *(const float4*)(g_dx + sl[n][e] * IND + q * 4));
    float4 s = f4red4(a0, a1);
    if (r == 0) {
        float dj = g_dis[j];
        s.x *= dj; s.y *= dj; s.z *= dj; s.w *= dj;
        *(float4*)(g_s + j * IND + q * 4) = s;
    }
}

// ---- 4: fused per-node MLP: y2 = dis .* (relu(s@W1 + b1) @ W2) ----
// Vectorized: W2 staged transposed; both GEMM phases use LDS.128 (4x fewer LDS).
__global__ void k_h1y2(const float* __restrict__ W1, const float* __restrict__ b1,
                       const float* __restrict__ W2) {
    __shared__ float ss[BNH][IND];        // 1 KB
    __shared__ float sh[BNH][HPAD];       // 16.6 KB
    __shared__ float w2t[NC][HPAD];       // 16.6 KB, w2t[cc][k] = W2[k*NC+cc]
    int jb = blockIdx.x * BNH;
    if (threadIdx.x < BNH * IND) ((float*)ss)[threadIdx.x] = g_s[jb * IND + threadIdx.x];
    #pragma unroll
    for (int u = 0; u < HID * NC / 256; u++) {
        int t = threadIdx.x + u * 256;
        w2t[t % NC][t / NC] = W2[t];      // coalesced gmem read, scattered smem write
    }
    __syncthreads();
    int c = threadIdx.x;
    float w[IND];
    #pragma unroll
    for (int k = 0; k < IND; k++) w[k] = __ldg(&W1[k * HID + c]);
    float bb = __ldg(&b1[c]);
    #pragma unroll
    for (int n = 0; n < BNH; n++) {
        float acc = bb;
        const float4* sr = (const float4*)ss[n];      // broadcast LDS.128
        #pragma unroll
        for (int k4 = 0; k4 < IND / 4; k4++) {
            float4 v = sr[k4];
            acc += v.x * w[k4 * 4 + 0] + v.y * w[k4 * 4 + 1]
                 + v.z * w[k4 * 4 + 2] + v.w * w[k4 * 4 + 3];
        }
        sh[n][c] = fmaxf(acc, 0.0f);
    }
    __syncthreads();
    int n = threadIdx.x / NC, cc = threadIdx.x % NC;
    const float4* hr = (const float4*)sh[n];          // broadcast within warp
    const float4* wr = (const float4*)w2t[cc];
    float acc = 0.0f;
    #pragma unroll 16
    for (int k4 = 0; k4 < HID / 4; k4++) {
        float4 h = hr[k4];
        float4 v = wr[k4];
        acc += h.x * v.x + h.y * v.y + h.z * v.z + h.w * v.w;
    }
    int j = jb + n;
    g_y2[j * NC + cc] = g_dis[j] * acc;
}

// ---- 5: layer-2 aggregation + bias + skip(x) -> logits in d_out ----
__global__ void k_agg2(const float* __restrict__ x, const float* __restrict__ b2,
                       float* __restrict__ out) {
    __shared__ int sl[NPBA][STRIDE];
    __shared__ int sdd[NPBA];
    int jb = blockIdx.x * NPBA;
    for (int t = threadIdx.x; t < NPBA * STRIDE; t += blockDim.x)
        ((int*)sl)[t] = g_rows[jb * STRIDE + t];
    if (threadIdx.x < NPBA) sdd[threadIdx.x] = min(g_cnt[jb + threadIdx.x], STRIDE);
    __syncthreads();
    int n = threadIdx.x >> 4;
    int r = (threadIdx.x >> 2) & 3;
    int q = threadIdx.x & 3;
    int j = jb + n;
    int d = sdd[n];
    float4 a0 = make_float4(0.f, 0.f, 0.f, 0.f), a1 = a0;
    if (r == 0) a0 = *(const float4*)(g_y2 + j * NC + q * 4);    // self loop
    int e = r;
    for (; e + 4 < d; e += 8) {
        const float4 v0 = *(const float4*)(g_y2 + sl[n][e]     * NC + q * 4);
        const float4 v1 = *(const float4*)(g_y2 + sl[n][e + 4] * NC + q * 4);
        f4add(a0, v0); f4add(a1, v1);
    }
    if (e < d) f4add(a0, *(const float4*)(g_y2 + sl[n][e] * NC + q * 4));
    float4 s = f4red4(a0, a1);
    if (r == 0) {
        float dj = g_dis[j];
        const float4 xb = *(const float4*)(x + j * IND + q * 4);
        const float4 bb = *(const float4*)(b2 + q * 4);
        float4 rr;
        rr.x = dj * s.x + bb.x + xb.x;
        rr.y = dj * s.y + bb.y + xb.y;
        rr.z = dj * s.z + bb.z + xb.z;
        rr.w = dj * s.w + bb.w + xb.w;
        *(float4*)(out + j * NC + q * 4) = rr;
    }
}

// ---- 6: per-class (axis=0) max and sum(exp) ----
__global__ void k_colreduce(const float* __restrict__ out) {
    int c = blockIdx.x;
    __shared__ float red[256];
    float m = -1e30f;
    for (int j = threadIdx.x; j < NN; j += 256) m = fmaxf(m, out[j * NC + c]);
    red[threadIdx.x] = m; __syncthreads();
    for (int s = 128; s > 0; s >>= 1) {
        if (threadIdx.x < s) red[threadIdx.x] = fmaxf(red[threadIdx.x], red[threadIdx.x + s]);
        __syncthreads();
    }
    m = red[0]; __syncthreads();
    float s = 0.0f;
    for (int j = threadIdx.x; j < NN; j += 256) s += expf(out[j * NC + c] - m);
    red[threadIdx.x] = s; __syncthreads();
    for (int st = 128; st > 0; st >>= 1) {
        if (threadIdx.x < st) red[threadIdx.x] += red[threadIdx.x + st];
        __syncthreads();
    }
    if (threadIdx.x == 0) { g_cmax[c] = m; g_csum[c] = red[0]; }
}

// ---- 7: normalize in place + re-zero counters for the next graph replay ----
__global__ void k_softmax(float* __restrict__ out) {
    int t = blockIdx.x * blockDim.x + threadIdx.x;
    if (t < NN) g_cnt[t] = 0;          // statics start zeroed; every run ends zeroed
    if (t < NN * NC) {
        int c = t & (NC - 1);
        out[t] = expf(out[t] - g_cmax[c]) / g_csum[c];
    }
}

extern "C" void kernel_launch(void* const* d_in, const int* in_sizes, int n_in,
                              void* d_out, int out_size) {
    const float* A  = (const float*)d_in[0];
    const float* x  = (const float*)d_in[1];
    const float* W1 = (const float*)d_in[2];
    const float* b1 = (const float*)d_in[3];
    const float* W2 = (const float*)d_in[4];
    const float* b2 = (const float*)d_in[5];
    float* out = (float*)d_out;

    k_extract<<<NN, 256>>>(A);
    k_prep<<<(NN + 255) / 256, 256>>>(x);
    k_xagg<<<NN / NPBA, NPBA * 16>>>();
    k_h1y2<<<NN / BNH, HID>>>(W1, b1, W2);
    k_agg2<<<NN / NPBA, NPBA * 16>>>(x, b2, out);
    k_colreduce<<<NC, 256>>>(out);
    k_softmax<<<(NN * NC + 255) / 256, 256>>>(out);
}